// round 16
// baseline (speedup 1.0000x reference)
#include <cuda_runtime.h>
#include <cuda_fp16.h>
#include <math.h>
#include <stdint.h>

// Problem constants
#define BATCH 2
#define NSEQ 2048
#define DIM 1024
#define HEADS 16
#define DHEAD 64
#define INNER (HEADS * DHEAD)      // 1024
#define QKV_W (3 * INNER)          // 3072
#define ROWS (BATCH * NSEQ)        // 4096
#define SCALE 0.125f               // 64^-0.5
#define LN_EPS 1e-5f
#define LOG2E 1.4426950408889634f

// Scratch (device globals: allocation-free rule) — all fp16
__device__ __half g_xn[ROWS * DIM];        //  8 MB
__device__ __half g_qkv[ROWS * QKV_W];     // 24 MB
__device__ __half g_attn[ROWS * INNER];    //  8 MB
__device__ __half g_wqkvT[QKV_W * DIM];    //  6 MB (transposed [N][K])
__device__ __half g_woutT[DIM * INNER];    //  2 MB (transposed [N][K])

// ---------------------------------------------------------------------------
// helpers
// ---------------------------------------------------------------------------
__device__ __forceinline__ float exp2_fast(float x) {
    float y;
    asm("ex2.approx.ftz.f32 %0, %1;" : "=f"(y) : "f"(x));
    return y;
}
__device__ __forceinline__ uint32_t pack_h2(float lo, float hi) {
    uint32_t d;
    asm("cvt.rn.f16x2.f32 %0, %1, %2;" : "=r"(d) : "f"(hi), "f"(lo));
    return d;
}
__device__ __forceinline__ float2 unpack_h2(uint32_t u) {
    __half2 h = *reinterpret_cast<__half2*>(&u);
    return __half22float2(h);
}

__device__ __forceinline__ void mma_f16(float c[4],
                                        uint32_t a0, uint32_t a1, uint32_t a2, uint32_t a3,
                                        uint32_t b0, uint32_t b1) {
    asm volatile(
        "mma.sync.aligned.m16n8k16.row.col.f32.f16.f16.f32 "
        "{%0,%1,%2,%3}, {%4,%5,%6,%7}, {%8,%9}, {%0,%1,%2,%3};"
        : "+f"(c[0]), "+f"(c[1]), "+f"(c[2]), "+f"(c[3])
        : "r"(a0), "r"(a1), "r"(a2), "r"(a3), "r"(b0), "r"(b1));
}

__device__ __forceinline__ void ldsm_x4(uint32_t r[4], uint32_t addr) {
    asm volatile("ldmatrix.sync.aligned.m8n8.x4.shared.b16 {%0,%1,%2,%3}, [%4];"
                 : "=r"(r[0]), "=r"(r[1]), "=r"(r[2]), "=r"(r[3]) : "r"(addr));
}
__device__ __forceinline__ void ldsm_x4_t(uint32_t r[4], uint32_t addr) {
    asm volatile("ldmatrix.sync.aligned.m8n8.x4.trans.shared.b16 {%0,%1,%2,%3}, [%4];"
                 : "=r"(r[0]), "=r"(r[1]), "=r"(r[2]), "=r"(r[3]) : "r"(addr));
}

__device__ __forceinline__ void cp_async16(uint32_t dst, const void* src) {
    asm volatile("cp.async.cg.shared.global [%0], [%1], 16;" :: "r"(dst), "l"(src));
}
__device__ __forceinline__ void cp_commit() {
    asm volatile("cp.async.commit_group;");
}
template <int N>
__device__ __forceinline__ void cp_wait() {
    asm volatile("cp.async.wait_group %0;" :: "n"(N));
}

// ---------------------------------------------------------------------------
// fused preprocessing: both weight transposes + LayerNorm in ONE launch.
// ---------------------------------------------------------------------------
#define NT1 ((QKV_W / 32) * (DIM / 32))     // 3072
#define NT2 ((DIM / 32) * (INNER / 32))     // 1024

__device__ void transpose_tile(const float* __restrict__ src, __half* __restrict__ dst,
                               int R, int C, int bx, int by)
{
    __shared__ float t[32][33];
    const int tx = threadIdx.x & 31;
    const int ty = threadIdx.x >> 5;

    #pragma unroll
    for (int i = 0; i < 4; i++)
        t[ty + i * 8][tx] = src[(size_t)(by + ty + i * 8) * C + bx + tx];
    __syncthreads();
    #pragma unroll
    for (int i = 0; i < 4; i++)
        dst[(size_t)(bx + ty + i * 8) * R + by + tx] = __float2half_rn(t[tx][ty + i * 8]);
}

__device__ void ln_row(const float* __restrict__ x,
                       const float* __restrict__ gamma,
                       const float* __restrict__ beta,
                       __half* __restrict__ xn, int row)
{
    __shared__ float red[8];
    const int tid = threadIdx.x;
    const float* xr = x + (size_t)row * DIM;

    float4 v = *(const float4*)(xr + tid * 4);

    float s = v.x + v.y + v.z + v.w;
    #pragma unroll
    for (int o = 16; o > 0; o >>= 1) s += __shfl_xor_sync(0xffffffffu, s, o);
    if ((tid & 31) == 0) red[tid >> 5] = s;
    __syncthreads();
    if (tid < 8) {
        float t = red[tid];
        #pragma unroll
        for (int o = 4; o > 0; o >>= 1) t += __shfl_xor_sync(0xffu, t, o);
        if (tid == 0) red[0] = t;
    }
    __syncthreads();
    const float mu = red[0] * (1.0f / DIM);
    __syncthreads();

    float d0 = v.x - mu, d1 = v.y - mu, d2 = v.z - mu, d3 = v.w - mu;
    float sq = d0 * d0 + d1 * d1 + d2 * d2 + d3 * d3;
    #pragma unroll
    for (int o = 16; o > 0; o >>= 1) sq += __shfl_xor_sync(0xffffffffu, sq, o);
    if ((tid & 31) == 0) red[tid >> 5] = sq;
    __syncthreads();
    if (tid < 8) {
        float t = red[tid];
        #pragma unroll
        for (int o = 4; o > 0; o >>= 1) t += __shfl_xor_sync(0xffu, t, o);
        if (tid == 0) red[0] = t;
    }
    __syncthreads();
    const float inv = rsqrtf(red[0] * (1.0f / DIM) + LN_EPS);

    const int c = tid * 4;
    float4 g = *(const float4*)(gamma + c);
    float4 b = *(const float4*)(beta + c);
    uint2 o;
    o.x = pack_h2(d0 * inv * g.x + b.x, d1 * inv * g.y + b.y);
    o.y = pack_h2(d2 * inv * g.z + b.z, d3 * inv * g.w + b.w);
    *(uint2*)(xn + (size_t)row * DIM + c) = o;
}

__global__ __launch_bounds__(256) void prep_kernel(
    const float* __restrict__ x,
    const float* __restrict__ gamma,
    const float* __restrict__ beta,
    const float* __restrict__ w_qkv,
    const float* __restrict__ w_out,
    __half* __restrict__ xn,
    __half* __restrict__ wqkvT,
    __half* __restrict__ woutT)
{
    const int bid = blockIdx.x;
    if (bid < NT1) {
        const int bx = (bid % (QKV_W / 32)) * 32;
        const int by = (bid / (QKV_W / 32)) * 32;
        transpose_tile(w_qkv, wqkvT, DIM, QKV_W, bx, by);
    } else if (bid < NT1 + NT2) {
        const int id = bid - NT1;
        const int bx = (id % (DIM / 32)) * 32;
        const int by = (id / (DIM / 32)) * 32;
        transpose_tile(w_out, woutT, INNER, DIM, bx, by);
    } else {
        ln_row(x, gamma, beta, xn, bid - NT1 - NT2);
    }
}

// ---------------------------------------------------------------------------
// FP16 tensor-core GEMM (m16n8k16), 128x128 tile, 128 threads (4 warps,
// 2m x 2n, warp tile m64 x n64). Each ldsm fragment feeds 4 mma -> read
// traffic 0.0625 B/MAC (smem crossbar no longer binding).
// cp.async TRIPLE buffer, BK=64 halves, ONE __syncthreads per slab.
// C[M,N] = A[M,K] @ B^T; A f16 [M][K], B f16 transposed [N][K].
// ---------------------------------------------------------------------------
#define LDT2 72
#define STAGE_H (128 * LDT2)
__global__ __launch_bounds__(128) void f16_gemm(
    int M, int N, int K, int outHalf,
    const __half* __restrict__ A,
    const __half* __restrict__ B,
    void* __restrict__ Cv)
{
    __shared__ __half As[3][STAGE_H];
    __shared__ __half Bs[3][STAGE_H];

    const int tid  = threadIdx.x;
    const int warp = tid >> 5;           // 0..3
    const int lane = tid & 31;
    const int lr = lane >> 2;
    const int lc = lane & 3;

    const int wm = (warp & 1) * 64;      // 2 m-warps
    const int wn = (warp >> 1) * 64;     // 2 n-warps

    A += (size_t)blockIdx.y * 128 * K;
    B += (size_t)blockIdx.x * 128 * K;
    const size_t cOff = (size_t)blockIdx.y * 128 * N + blockIdx.x * 128;

    // loader: 1024 16B-chunks per matrix per slab; 8 per thread per matrix
    const int r0 = tid >> 3;             // 0..15
    const int kc = (tid & 7) * 8;        // half-col 0..56

    const uint32_t asBase = (uint32_t)__cvta_generic_to_shared(As);
    const uint32_t bsBase = (uint32_t)__cvta_generic_to_shared(Bs);

    const int nSlab = K / 64;

    auto load_slab = [&](int s, int buf) {
        const int gk = s * 64 + kc;
        const uint32_t ad = asBase + (uint32_t)(buf * STAGE_H * 2);
        const uint32_t bd = bsBase + (uint32_t)(buf * STAGE_H * 2);
        #pragma unroll
        for (int i = 0; i < 8; i++) {
            const int r = r0 + i * 16;
            cp_async16(ad + (uint32_t)((r * LDT2 + kc) * 2), A + (size_t)r * K + gk);
            cp_async16(bd + (uint32_t)((r * LDT2 + kc) * 2), B + (size_t)r * K + gk);
        }
    };

    const int aoff = (wm + (lane & 15)) * LDT2 + ((lane >> 4) << 3);
    const int boff = (wn + ((lane >> 4) << 3) + (lane & 7)) * LDT2 + (((lane >> 3) & 1) << 3);

    float acc[4][8][4] = {};

    load_slab(0, 0); cp_commit();
    load_slab(1, 1); cp_commit();

    for (int s = 0; s < nSlab; s++) {
        const int cur = s % 3;

        cp_wait<1>();
        __syncthreads();         // the ONLY barrier per slab

        const uint32_t aStage = asBase + (uint32_t)(cur * STAGE_H * 2);
        const uint32_t bStage = bsBase + (uint32_t)(cur * STAGE_H * 2);

        #pragma unroll
        for (int ks = 0; ks < 64; ks += 16) {
            uint32_t afr[4][4];
            #pragma unroll
            for (int mi = 0; mi < 4; mi++)
                ldsm_x4(afr[mi], aStage + (uint32_t)((aoff + mi * 16 * LDT2 + ks) * 2));
            uint32_t bfr[4][4];
            #pragma unroll
            for (int j = 0; j < 4; j++)
                ldsm_x4(bfr[j], bStage + (uint32_t)((boff + j * 16 * LDT2 + ks) * 2));
            #pragma unroll
            for (int mi = 0; mi < 4; mi++)
                #pragma unroll
                for (int j = 0; j < 4; j++) {
                    mma_f16(acc[mi][2 * j],     afr[mi][0], afr[mi][1], afr[mi][2], afr[mi][3],
                            bfr[j][0], bfr[j][1]);
                    mma_f16(acc[mi][2 * j + 1], afr[mi][0], afr[mi][1], afr[mi][2], afr[mi][3],
                            bfr[j][2], bfr[j][3]);
                }
        }

        if (s + 2 < nSlab) load_slab(s + 2, (s + 2) % 3);
        cp_commit();
    }

    if (outHalf) {
        __half* C = (__half*)Cv + cOff;
        #pragma unroll
        for (int mi = 0; mi < 4; mi++) {
            const int r = wm + 16 * mi + lr;
            #pragma unroll
            for (int ni = 0; ni < 8; ni++) {
                const int c0 = wn + 8 * ni + 2 * lc;
                *(uint32_t*)(C + (size_t)r * N + c0)       = pack_h2(acc[mi][ni][0], acc[mi][ni][1]);
                *(uint32_t*)(C + (size_t)(r + 8) * N + c0) = pack_h2(acc[mi][ni][2], acc[mi][ni][3]);
            }
        }
    } else {
        float* C = (float*)Cv + cOff;
        #pragma unroll
        for (int mi = 0; mi < 4; mi++) {
            const int r = wm + 16 * mi + lr;
            #pragma unroll
            for (int ni = 0; ni < 8; ni++) {
                const int c0 = wn + 8 * ni + 2 * lc;
                *(float2*)(C + (size_t)r * N + c0)       = make_float2(acc[mi][ni][0], acc[mi][ni][1]);
                *(float2*)(C + (size_t)(r + 8) * N + c0) = make_float2(acc[mi][ni][2], acc[mi][ni][3]);
            }
        }
    }
}

// ---------------------------------------------------------------------------
// FlashAttention, FP16 mma, exact softmax, cp.async triple buffer.
// 4 warps (128 thr), each warp m32 (two m16 tiles). (R13 config — best.)
// ---------------------------------------------------------------------------
__global__ __launch_bounds__(128) void attn_mma_kernel(
    const __half* __restrict__ qkv,
    __half* __restrict__ attn_out)
{
    const int bh = blockIdx.y;
    const int b = bh / HEADS;
    const int h = bh % HEADS;
    const int qbase = blockIdx.x * 128;
    const int warp = threadIdx.x >> 5;
    const int lane = threadIdx.x & 31;
    const int lr = lane >> 2;
    const int lc = lane & 3;

    __shared__ __half Ks[3][64][LDT2];
    __shared__ __half Vs[3][64][LDT2];

    const __half* base = qkv + (size_t)b * NSEQ * QKV_W;
    const float NEG_INF = __int_as_float(0xff800000);
    const float QSCALE = SCALE * LOG2E;

    const int diagTile = blockIdx.x * 2 + (warp >> 1);

    const uint32_t ksBase = (uint32_t)__cvta_generic_to_shared(Ks);
    const uint32_t vsBase = (uint32_t)__cvta_generic_to_shared(Vs);
    const uint32_t TILE_B = (uint32_t)(64 * LDT2 * 2);

    auto load_tile = [&](int kt, int buf) {
        #pragma unroll
        for (int it = 0; it < 4; it++) {
            const int idx = threadIdx.x + it * 128;
            const int r  = idx >> 3;
            const int cc = (idx & 7) * 8;
            const __half* src = base + (size_t)(kt + r) * QKV_W + INNER + h * DHEAD + cc;
            const uint32_t off = (uint32_t)(buf) * TILE_B + (uint32_t)((r * LDT2 + cc) * 2);
            cp_async16(ksBase + off, src);
            cp_async16(vsBase + off, src + INNER);
        }
    };

    const int koff = (((lane >> 4) << 3) + (lane & 7)) * LDT2 + (((lane >> 3) & 1) << 3);
    const int voff = ((((lane >> 3) & 1) << 3) + (lane & 7)) * LDT2 + ((lane >> 4) << 3);

    uint32_t qa[2][4][4];
    #pragma unroll
    for (int mi = 0; mi < 2; mi++) {
        const int r0 = qbase + 32 * warp + 16 * mi + lr;
        const __half* q0 = base + (size_t)r0 * QKV_W + h * DHEAD;
        const __half* q1 = q0 + (size_t)8 * QKV_W;
        #pragma unroll
        for (int s = 0; s < 4; s++) {
            const int d0 = 16 * s + 2 * lc;
            qa[mi][s][0] = pack_h2(__half2float(q0[d0])     * QSCALE, __half2float(q0[d0 + 1]) * QSCALE);
            qa[mi][s][1] = pack_h2(__half2float(q1[d0])     * QSCALE, __half2float(q1[d0 + 1]) * QSCALE);
            qa[mi][s][2] = pack_h2(__half2float(q0[d0 + 8]) * QSCALE, __half2float(q0[d0 + 9]) * QSCALE);
            qa[mi][s][3] = pack_h2(__half2float(q1[d0 + 8]) * QSCALE, __half2float(q1[d0 + 9]) * QSCALE);
        }
    }

    float oa[2][8][4] = {};
    float l0[2] = {0.0f, 0.0f}, l1[2] = {0.0f, 0.0f};

    const int nTile = NSEQ / 64;
    load_tile(0, 0); cp_commit();
    load_tile(64, 1); cp_commit();

    for (int ti = 0; ti < nTile; ti++) {
        const int cur = ti % 3;

        cp_wait<1>();
        __syncthreads();

        const uint32_t kStage = ksBase + (uint32_t)cur * TILE_B;
        const uint32_t vStage = vsBase + (uint32_t)cur * TILE_B;

        float sfr[2][8][4] = {};
        #pragma unroll
        for (int s = 0; s < 4; s++) {
            #pragma unroll
            for (int j = 0; j < 4; j++) {
                uint32_t kb[4];
                ldsm_x4(kb, kStage + (uint32_t)((16 * j * LDT2 + koff + 16 * s) * 2));
                #pragma unroll
                for (int mi = 0; mi < 2; mi++) {
                    mma_f16(sfr[mi][2 * j],     qa[mi][s][0], qa[mi][s][1], qa[mi][s][2], qa[mi][s][3],
                            kb[0], kb[1]);
                    mma_f16(sfr[mi][2 * j + 1], qa[mi][s][0], qa[mi][s][1], qa[mi][s][2], qa[mi][s][3],
                            kb[2], kb[3]);
                }
            }
        }

        if (ti == diagTile) {
            #pragma unroll
            for (int mi = 0; mi < 2; mi++) {
                const int rloc0 = ((warp & 1) << 5) + (mi << 4) + lr;
                const int rloc1 = rloc0 + 8;
                #pragma unroll
                for (int n = 0; n < 8; n++) {
                    const int col0 = 8 * n + 2 * lc;
                    if (col0 == rloc0)     sfr[mi][n][0] = NEG_INF;
                    if (col0 + 1 == rloc0) sfr[mi][n][1] = NEG_INF;
                    if (col0 == rloc1)     sfr[mi][n][2] = NEG_INF;
                    if (col0 + 1 == rloc1) sfr[mi][n][3] = NEG_INF;
                }
            }
        }

        uint32_t pa[2][4][4];
        #pragma unroll
        for (int mi = 0; mi < 2; mi++) {
            #pragma unroll
            for (int s = 0; s < 4; s++) {
                pa[mi][s][0] = pack_h2(exp2_fast(sfr[mi][2 * s][0]),     exp2_fast(sfr[mi][2 * s][1]));
                pa[mi][s][1] = pack_h2(exp2_fast(sfr[mi][2 * s][2]),     exp2_fast(sfr[mi][2 * s][3]));
                pa[mi][s][2] = pack_h2(exp2_fast(sfr[mi][2 * s + 1][0]), exp2_fast(sfr[mi][2 * s + 1][1]));
                pa[mi][s][3] = pack_h2(exp2_fast(sfr[mi][2 * s + 1][2]), exp2_fast(sfr[mi][2 * s + 1][3]));
                float2 f0 = unpack_h2(pa[mi][s][0]);
                float2 f1 = unpack_h2(pa[mi][s][1]);
                float2 f2 = unpack_h2(pa[mi][s][2]);
                float2 f3 = unpack_h2(pa[mi][s][3]);
                l0[mi] += f0.x + f0.y + f2.x + f2.y;
                l1[mi] += f1.x + f1.y + f3.x + f3.y;
            }
        }

        #pragma unroll
        for (int s = 0; s < 4; s++) {
            #pragma unroll
            for (int j = 0; j < 4; j++) {
                uint32_t vb[4];
                ldsm_x4_t(vb, vStage + (uint32_t)((16 * s * LDT2 + voff + 16 * j) * 2));
                #pragma unroll
                for (int mi = 0; mi < 2; mi++) {
                    mma_f16(oa[mi][2 * j],     pa[mi][s][0], pa[mi][s][1], pa[mi][s][2], pa[mi][s][3],
                            vb[0], vb[1]);
                    mma_f16(oa[mi][2 * j + 1], pa[mi][s][0], pa[mi][s][1], pa[mi][s][2], pa[mi][s][3],
                            vb[2], vb[3]);
                }
            }
        }

        if (ti + 2 < nTile) load_tile((ti + 2) * 64, (ti + 2) % 3);
        cp_commit();
    }

    #pragma unroll
    for (int mi = 0; mi < 2; mi++) {
        l0[mi] += __shfl_xor_sync(0xffffffffu, l0[mi], 1);
        l0[mi] += __shfl_xor_sync(0xffffffffu, l0[mi], 2);
        l1[mi] += __shfl_xor_sync(0xffffffffu, l1[mi], 1);
        l1[mi] += __shfl_xor_sync(0xffffffffu, l1[mi], 2);
        const float inv0 = 1.0f / l0[mi];
        const float inv1 = 1.0f / l1[mi];

        const int row0 = qbase + 32 * warp + 16 * mi + lr;
        __half* o0 = attn_out + ((size_t)b * NSEQ + row0) * INNER + h * DHEAD;
        __half* o1 = o0 + (size_t)8 * INNER;
        #pragma unroll
        for (int n = 0; n < 8; n++) {
            const int c = 8 * n + 2 * lc;
            *(uint32_t*)(o0 + c) = pack_h2(oa[mi][n][0] * inv0, oa[mi][n][1] * inv0);
            *(uint32_t*)(o1 + c) = pack_h2(oa[mi][n][2] * inv1, oa[mi][n][3] * inv1);
        }
    }
}

// ---------------------------------------------------------------------------
extern "C" void kernel_launch(void* const* d_in, const int* in_sizes, int n_in,
                              void* d_out, int out_size)
{
    const float* x      = (const float*)d_in[0];
    const float* gamma  = (const float*)d_in[1];
    const float* beta   = (const float*)d_in[2];
    const float* w_qkv  = (const float*)d_in[3];
    const float* w_out  = (const float*)d_in[4];
    float* out = (float*)d_out;

    __half *xn, *qkv, *attn, *wqkvT, *woutT;
    cudaGetSymbolAddress((void**)&xn,    g_xn);
    cudaGetSymbolAddress((void**)&qkv,   g_qkv);
    cudaGetSymbolAddress((void**)&attn,  g_attn);
    cudaGetSymbolAddress((void**)&wqkvT, g_wqkvT);
    cudaGetSymbolAddress((void**)&woutT, g_woutT);

    // 0+1) fused: weight transposes + LayerNorm (one launch)
    prep_kernel<<<NT1 + NT2 + ROWS, 256>>>(x, gamma, beta, w_qkv, w_out,
                                           xn, wqkvT, woutT);

    // 2) QKV projection: [4096,1024] @ [1024,3072], fp16 output
    {
        dim3 grid(QKV_W / 128, ROWS / 128);
        f16_gemm<<<grid, 128>>>(ROWS, QKV_W, DIM, 1, xn, wqkvT, qkv);
    }

    // 3) attention (128 q-rows per block, 4 warps x m32)
    {
        dim3 grid(NSEQ / 128, BATCH * HEADS);
        attn_mma_kernel<<<grid, 128>>>(qkv, attn);
    }

    // 4) output projection: [4096,1024] @ [1024,1024], fp32 output
    {
        dim3 grid(DIM / 128, ROWS / 128);
        f16_gemm<<<grid, 128>>>(ROWS, DIM, INNER, 0, attn, woutT, out);
    }
}

// round 17
// speedup vs baseline: 1.0106x; 1.0106x over previous
#include <cuda_runtime.h>
#include <cuda_fp16.h>
#include <math.h>
#include <stdint.h>

// Problem constants
#define BATCH 2
#define NSEQ 2048
#define DIM 1024
#define HEADS 16
#define DHEAD 64
#define INNER (HEADS * DHEAD)      // 1024
#define QKV_W (3 * INNER)          // 3072
#define ROWS (BATCH * NSEQ)        // 4096
#define SCALE 0.125f               // 64^-0.5
#define LN_EPS 1e-5f
#define LOG2E 1.4426950408889634f

// Scratch (device globals: allocation-free rule) — all fp16
__device__ __half g_xn[ROWS * DIM];        //  8 MB
__device__ __half g_qkv[ROWS * QKV_W];     // 24 MB
__device__ __half g_attn[ROWS * INNER];    //  8 MB
__device__ __half g_wqkvT[QKV_W * DIM];    //  6 MB (transposed [N][K])
__device__ __half g_woutT[DIM * INNER];    //  2 MB (transposed [N][K])

// ---------------------------------------------------------------------------
// helpers
// ---------------------------------------------------------------------------
__device__ __forceinline__ float exp2_fast(float x) {
    float y;
    asm("ex2.approx.ftz.f32 %0, %1;" : "=f"(y) : "f"(x));
    return y;
}
__device__ __forceinline__ uint32_t pack_h2(float lo, float hi) {
    uint32_t d;
    asm("cvt.rn.f16x2.f32 %0, %1, %2;" : "=r"(d) : "f"(hi), "f"(lo));
    return d;
}
__device__ __forceinline__ float2 unpack_h2(uint32_t u) {
    __half2 h = *reinterpret_cast<__half2*>(&u);
    return __half22float2(h);
}

__device__ __forceinline__ void mma_f16(float c[4],
                                        uint32_t a0, uint32_t a1, uint32_t a2, uint32_t a3,
                                        uint32_t b0, uint32_t b1) {
    asm volatile(
        "mma.sync.aligned.m16n8k16.row.col.f32.f16.f16.f32 "
        "{%0,%1,%2,%3}, {%4,%5,%6,%7}, {%8,%9}, {%0,%1,%2,%3};"
        : "+f"(c[0]), "+f"(c[1]), "+f"(c[2]), "+f"(c[3])
        : "r"(a0), "r"(a1), "r"(a2), "r"(a3), "r"(b0), "r"(b1));
}

__device__ __forceinline__ void ldsm_x4(uint32_t r[4], uint32_t addr) {
    asm volatile("ldmatrix.sync.aligned.m8n8.x4.shared.b16 {%0,%1,%2,%3}, [%4];"
                 : "=r"(r[0]), "=r"(r[1]), "=r"(r[2]), "=r"(r[3]) : "r"(addr));
}
__device__ __forceinline__ void ldsm_x4_t(uint32_t r[4], uint32_t addr) {
    asm volatile("ldmatrix.sync.aligned.m8n8.x4.trans.shared.b16 {%0,%1,%2,%3}, [%4];"
                 : "=r"(r[0]), "=r"(r[1]), "=r"(r[2]), "=r"(r[3]) : "r"(addr));
}

__device__ __forceinline__ void cp_async16(uint32_t dst, const void* src) {
    asm volatile("cp.async.cg.shared.global [%0], [%1], 16;" :: "r"(dst), "l"(src));
}
__device__ __forceinline__ void cp_commit() {
    asm volatile("cp.async.commit_group;");
}
template <int N>
__device__ __forceinline__ void cp_wait() {
    asm volatile("cp.async.wait_group %0;" :: "n"(N));
}

// ---------------------------------------------------------------------------
// fused preprocessing: both weight transposes + LayerNorm in ONE launch.
// ---------------------------------------------------------------------------
#define NT1 ((QKV_W / 32) * (DIM / 32))     // 3072
#define NT2 ((DIM / 32) * (INNER / 32))     // 1024

__device__ void transpose_tile(const float* __restrict__ src, __half* __restrict__ dst,
                               int R, int C, int bx, int by)
{
    __shared__ float t[32][33];
    const int tx = threadIdx.x & 31;
    const int ty = threadIdx.x >> 5;

    #pragma unroll
    for (int i = 0; i < 4; i++)
        t[ty + i * 8][tx] = src[(size_t)(by + ty + i * 8) * C + bx + tx];
    __syncthreads();
    #pragma unroll
    for (int i = 0; i < 4; i++)
        dst[(size_t)(bx + ty + i * 8) * R + by + tx] = __float2half_rn(t[tx][ty + i * 8]);
}

__device__ void ln_row(const float* __restrict__ x,
                       const float* __restrict__ gamma,
                       const float* __restrict__ beta,
                       __half* __restrict__ xn, int row)
{
    __shared__ float red[8];
    const int tid = threadIdx.x;
    const float* xr = x + (size_t)row * DIM;

    float4 v = *(const float4*)(xr + tid * 4);

    float s = v.x + v.y + v.z + v.w;
    #pragma unroll
    for (int o = 16; o > 0; o >>= 1) s += __shfl_xor_sync(0xffffffffu, s, o);
    if ((tid & 31) == 0) red[tid >> 5] = s;
    __syncthreads();
    if (tid < 8) {
        float t = red[tid];
        #pragma unroll
        for (int o = 4; o > 0; o >>= 1) t += __shfl_xor_sync(0xffu, t, o);
        if (tid == 0) red[0] = t;
    }
    __syncthreads();
    const float mu = red[0] * (1.0f / DIM);
    __syncthreads();

    float d0 = v.x - mu, d1 = v.y - mu, d2 = v.z - mu, d3 = v.w - mu;
    float sq = d0 * d0 + d1 * d1 + d2 * d2 + d3 * d3;
    #pragma unroll
    for (int o = 16; o > 0; o >>= 1) sq += __shfl_xor_sync(0xffffffffu, sq, o);
    if ((tid & 31) == 0) red[tid >> 5] = sq;
    __syncthreads();
    if (tid < 8) {
        float t = red[tid];
        #pragma unroll
        for (int o = 4; o > 0; o >>= 1) t += __shfl_xor_sync(0xffu, t, o);
        if (tid == 0) red[0] = t;
    }
    __syncthreads();
    const float inv = rsqrtf(red[0] * (1.0f / DIM) + LN_EPS);

    const int c = tid * 4;
    float4 g = *(const float4*)(gamma + c);
    float4 b = *(const float4*)(beta + c);
    uint2 o;
    o.x = pack_h2(d0 * inv * g.x + b.x, d1 * inv * g.y + b.y);
    o.y = pack_h2(d2 * inv * g.z + b.z, d3 * inv * g.w + b.w);
    *(uint2*)(xn + (size_t)row * DIM + c) = o;
}

__global__ __launch_bounds__(256) void prep_kernel(
    const float* __restrict__ x,
    const float* __restrict__ gamma,
    const float* __restrict__ beta,
    const float* __restrict__ w_qkv,
    const float* __restrict__ w_out,
    __half* __restrict__ xn,
    __half* __restrict__ wqkvT,
    __half* __restrict__ woutT)
{
    const int bid = blockIdx.x;
    if (bid < NT1) {
        const int bx = (bid % (QKV_W / 32)) * 32;
        const int by = (bid / (QKV_W / 32)) * 32;
        transpose_tile(w_qkv, wqkvT, DIM, QKV_W, bx, by);
    } else if (bid < NT1 + NT2) {
        const int id = bid - NT1;
        const int bx = (id % (DIM / 32)) * 32;
        const int by = (id / (DIM / 32)) * 32;
        transpose_tile(w_out, woutT, INNER, DIM, bx, by);
    } else {
        ln_row(x, gamma, beta, xn, bid - NT1 - NT2);
    }
}

// ---------------------------------------------------------------------------
// FP16 tensor-core GEMM (m16n8k16), 128x128 tile, 256 thr (8 warps, 4m x 2n),
// cp.async TRIPLE buffer, BK=64 halves, ONE __syncthreads per slab.
// PERSISTENT CTAs: grid = min(nTiles, 296); each CTA loops over tiles
// (removes CTA launch/drain cost at wave boundaries). End-of-tile
// cp_wait<0> + __syncthreads guards the next tile's prologue against the
// last slab's stage-0 reads.
// C[M,N] = A[M,K] @ B^T; A f16 [M][K], B f16 transposed [N][K].
// ---------------------------------------------------------------------------
#define LDT2 72
#define STAGE_H (128 * LDT2)
__global__ __launch_bounds__(256) void f16_gemm(
    int M, int N, int K, int outHalf,
    const __half* __restrict__ A,
    const __half* __restrict__ B,
    void* __restrict__ Cv)
{
    __shared__ __half As[3][STAGE_H];
    __shared__ __half Bs[3][STAGE_H];

    const int tid  = threadIdx.x;
    const int warp = tid >> 5;
    const int lane = tid & 31;
    const int lr = lane >> 2;
    const int lc = lane & 3;

    const int wm = (warp & 3) * 32;
    const int wn = (warp >> 2) * 64;

    const int r0 = tid >> 3;
    const int kc = (tid & 7) * 8;

    const uint32_t asBase = (uint32_t)__cvta_generic_to_shared(As);
    const uint32_t bsBase = (uint32_t)__cvta_generic_to_shared(Bs);

    const int nSlab = K / 64;
    const int nBx = N / 128;
    const int nTiles = (M / 128) * nBx;

    const int aoff = (wm + (lane & 15)) * LDT2 + ((lane >> 4) << 3);
    const int boff = (wn + ((lane >> 4) << 3) + (lane & 7)) * LDT2 + (((lane >> 3) & 1) << 3);

    const __half* At;
    const __half* Bt;

    auto load_slab = [&](int s, int buf) {
        const int gk = s * 64 + kc;
        const uint32_t ad = asBase + (uint32_t)(buf * STAGE_H * 2);
        const uint32_t bd = bsBase + (uint32_t)(buf * STAGE_H * 2);
        #pragma unroll
        for (int i = 0; i < 4; i++) {
            const int r = r0 + i * 32;
            cp_async16(ad + (uint32_t)((r * LDT2 + kc) * 2), At + (size_t)r * K + gk);
            cp_async16(bd + (uint32_t)((r * LDT2 + kc) * 2), Bt + (size_t)r * K + gk);
        }
    };

    for (int t = blockIdx.x; t < nTiles; t += gridDim.x) {
        const int by = t / nBx;
        const int bx = t % nBx;
        At = A + (size_t)by * 128 * K;
        Bt = B + (size_t)bx * 128 * K;
        const size_t cOff = (size_t)by * 128 * N + (size_t)bx * 128;

        float acc[2][8][4] = {};

        load_slab(0, 0); cp_commit();
        load_slab(1, 1); cp_commit();

        for (int s = 0; s < nSlab; s++) {
            const int cur = s % 3;

            cp_wait<1>();
            __syncthreads();         // the ONLY barrier per slab

            const uint32_t aStage = asBase + (uint32_t)(cur * STAGE_H * 2);
            const uint32_t bStage = bsBase + (uint32_t)(cur * STAGE_H * 2);

            #pragma unroll
            for (int ks = 0; ks < 64; ks += 16) {
                uint32_t afr[2][4];
                #pragma unroll
                for (int mi = 0; mi < 2; mi++)
                    ldsm_x4(afr[mi], aStage + (uint32_t)((aoff + mi * 16 * LDT2 + ks) * 2));
                uint32_t bfr[4][4];
                #pragma unroll
                for (int j = 0; j < 4; j++)
                    ldsm_x4(bfr[j], bStage + (uint32_t)((boff + j * 16 * LDT2 + ks) * 2));
                #pragma unroll
                for (int mi = 0; mi < 2; mi++)
                    #pragma unroll
                    for (int j = 0; j < 4; j++) {
                        mma_f16(acc[mi][2 * j],     afr[mi][0], afr[mi][1], afr[mi][2], afr[mi][3],
                                bfr[j][0], bfr[j][1]);
                        mma_f16(acc[mi][2 * j + 1], afr[mi][0], afr[mi][1], afr[mi][2], afr[mi][3],
                                bfr[j][2], bfr[j][3]);
                    }
            }

            if (s + 2 < nSlab) load_slab(s + 2, (s + 2) % 3);
            cp_commit();
        }

        // drain pending cp.async and make sure every warp is done with the
        // stage buffers before the next tile's prologue overwrites them
        cp_wait<0>();

        if (outHalf) {
            __half* C = (__half*)Cv + cOff;
            #pragma unroll
            for (int mi = 0; mi < 2; mi++) {
                const int r = wm + 16 * mi + lr;
                #pragma unroll
                for (int ni = 0; ni < 8; ni++) {
                    const int c0 = wn + 8 * ni + 2 * lc;
                    *(uint32_t*)(C + (size_t)r * N + c0)       = pack_h2(acc[mi][ni][0], acc[mi][ni][1]);
                    *(uint32_t*)(C + (size_t)(r + 8) * N + c0) = pack_h2(acc[mi][ni][2], acc[mi][ni][3]);
                }
            }
        } else {
            float* C = (float*)Cv + cOff;
            #pragma unroll
            for (int mi = 0; mi < 2; mi++) {
                const int r = wm + 16 * mi + lr;
                #pragma unroll
                for (int ni = 0; ni < 8; ni++) {
                    const int c0 = wn + 8 * ni + 2 * lc;
                    *(float2*)(C + (size_t)r * N + c0)       = make_float2(acc[mi][ni][0], acc[mi][ni][1]);
                    *(float2*)(C + (size_t)(r + 8) * N + c0) = make_float2(acc[mi][ni][2], acc[mi][ni][3]);
                }
            }
        }

        __syncthreads();   // all warps finished compute/epilogue before reuse
    }
}

// ---------------------------------------------------------------------------
// FlashAttention, FP16 mma, exact softmax, cp.async triple buffer.
// 4 warps (128 thr), each warp m32 (two m16 tiles). (R13 config — best.)
// ---------------------------------------------------------------------------
__global__ __launch_bounds__(128) void attn_mma_kernel(
    const __half* __restrict__ qkv,
    __half* __restrict__ attn_out)
{
    const int bh = blockIdx.y;
    const int b = bh / HEADS;
    const int h = bh % HEADS;
    const int qbase = blockIdx.x * 128;
    const int warp = threadIdx.x >> 5;
    const int lane = threadIdx.x & 31;
    const int lr = lane >> 2;
    const int lc = lane & 3;

    __shared__ __half Ks[3][64][LDT2];
    __shared__ __half Vs[3][64][LDT2];

    const __half* base = qkv + (size_t)b * NSEQ * QKV_W;
    const float NEG_INF = __int_as_float(0xff800000);
    const float QSCALE = SCALE * LOG2E;

    const int diagTile = blockIdx.x * 2 + (warp >> 1);

    const uint32_t ksBase = (uint32_t)__cvta_generic_to_shared(Ks);
    const uint32_t vsBase = (uint32_t)__cvta_generic_to_shared(Vs);
    const uint32_t TILE_B = (uint32_t)(64 * LDT2 * 2);

    auto load_tile = [&](int kt, int buf) {
        #pragma unroll
        for (int it = 0; it < 4; it++) {
            const int idx = threadIdx.x + it * 128;
            const int r  = idx >> 3;
            const int cc = (idx & 7) * 8;
            const __half* src = base + (size_t)(kt + r) * QKV_W + INNER + h * DHEAD + cc;
            const uint32_t off = (uint32_t)(buf) * TILE_B + (uint32_t)((r * LDT2 + cc) * 2);
            cp_async16(ksBase + off, src);
            cp_async16(vsBase + off, src + INNER);
        }
    };

    const int koff = (((lane >> 4) << 3) + (lane & 7)) * LDT2 + (((lane >> 3) & 1) << 3);
    const int voff = ((((lane >> 3) & 1) << 3) + (lane & 7)) * LDT2 + ((lane >> 4) << 3);

    uint32_t qa[2][4][4];
    #pragma unroll
    for (int mi = 0; mi < 2; mi++) {
        const int r0 = qbase + 32 * warp + 16 * mi + lr;
        const __half* q0 = base + (size_t)r0 * QKV_W + h * DHEAD;
        const __half* q1 = q0 + (size_t)8 * QKV_W;
        #pragma unroll
        for (int s = 0; s < 4; s++) {
            const int d0 = 16 * s + 2 * lc;
            qa[mi][s][0] = pack_h2(__half2float(q0[d0])     * QSCALE, __half2float(q0[d0 + 1]) * QSCALE);
            qa[mi][s][1] = pack_h2(__half2float(q1[d0])     * QSCALE, __half2float(q1[d0 + 1]) * QSCALE);
            qa[mi][s][2] = pack_h2(__half2float(q0[d0 + 8]) * QSCALE, __half2float(q0[d0 + 9]) * QSCALE);
            qa[mi][s][3] = pack_h2(__half2float(q1[d0 + 8]) * QSCALE, __half2float(q1[d0 + 9]) * QSCALE);
        }
    }

    float oa[2][8][4] = {};
    float l0[2] = {0.0f, 0.0f}, l1[2] = {0.0f, 0.0f};

    const int nTile = NSEQ / 64;
    load_tile(0, 0); cp_commit();
    load_tile(64, 1); cp_commit();

    for (int ti = 0; ti < nTile; ti++) {
        const int cur = ti % 3;

        cp_wait<1>();
        __syncthreads();

        const uint32_t kStage = ksBase + (uint32_t)cur * TILE_B;
        const uint32_t vStage = vsBase + (uint32_t)cur * TILE_B;

        float sfr[2][8][4] = {};
        #pragma unroll
        for (int s = 0; s < 4; s++) {
            #pragma unroll
            for (int j = 0; j < 4; j++) {
                uint32_t kb[4];
                ldsm_x4(kb, kStage + (uint32_t)((16 * j * LDT2 + koff + 16 * s) * 2));
                #pragma unroll
                for (int mi = 0; mi < 2; mi++) {
                    mma_f16(sfr[mi][2 * j],     qa[mi][s][0], qa[mi][s][1], qa[mi][s][2], qa[mi][s][3],
                            kb[0], kb[1]);
                    mma_f16(sfr[mi][2 * j + 1], qa[mi][s][0], qa[mi][s][1], qa[mi][s][2], qa[mi][s][3],
                            kb[2], kb[3]);
                }
            }
        }

        if (ti == diagTile) {
            #pragma unroll
            for (int mi = 0; mi < 2; mi++) {
                const int rloc0 = ((warp & 1) << 5) + (mi << 4) + lr;
                const int rloc1 = rloc0 + 8;
                #pragma unroll
                for (int n = 0; n < 8; n++) {
                    const int col0 = 8 * n + 2 * lc;
                    if (col0 == rloc0)     sfr[mi][n][0] = NEG_INF;
                    if (col0 + 1 == rloc0) sfr[mi][n][1] = NEG_INF;
                    if (col0 == rloc1)     sfr[mi][n][2] = NEG_INF;
                    if (col0 + 1 == rloc1) sfr[mi][n][3] = NEG_INF;
                }
            }
        }

        uint32_t pa[2][4][4];
        #pragma unroll
        for (int mi = 0; mi < 2; mi++) {
            #pragma unroll
            for (int s = 0; s < 4; s++) {
                pa[mi][s][0] = pack_h2(exp2_fast(sfr[mi][2 * s][0]),     exp2_fast(sfr[mi][2 * s][1]));
                pa[mi][s][1] = pack_h2(exp2_fast(sfr[mi][2 * s][2]),     exp2_fast(sfr[mi][2 * s][3]));
                pa[mi][s][2] = pack_h2(exp2_fast(sfr[mi][2 * s + 1][0]), exp2_fast(sfr[mi][2 * s + 1][1]));
                pa[mi][s][3] = pack_h2(exp2_fast(sfr[mi][2 * s + 1][2]), exp2_fast(sfr[mi][2 * s + 1][3]));
                float2 f0 = unpack_h2(pa[mi][s][0]);
                float2 f1 = unpack_h2(pa[mi][s][1]);
                float2 f2 = unpack_h2(pa[mi][s][2]);
                float2 f3 = unpack_h2(pa[mi][s][3]);
                l0[mi] += f0.x + f0.y + f2.x + f2.y;
                l1[mi] += f1.x + f1.y + f3.x + f3.y;
            }
        }

        #pragma unroll
        for (int s = 0; s < 4; s++) {
            #pragma unroll
            for (int j = 0; j < 4; j++) {
                uint32_t vb[4];
                ldsm_x4_t(vb, vStage + (uint32_t)((16 * s * LDT2 + voff + 16 * j) * 2));
                #pragma unroll
                for (int mi = 0; mi < 2; mi++) {
                    mma_f16(oa[mi][2 * j],     pa[mi][s][0], pa[mi][s][1], pa[mi][s][2], pa[mi][s][3],
                            vb[0], vb[1]);
                    mma_f16(oa[mi][2 * j + 1], pa[mi][s][0], pa[mi][s][1], pa[mi][s][2], pa[mi][s][3],
                            vb[2], vb[3]);
                }
            }
        }

        if (ti + 2 < nTile) load_tile((ti + 2) * 64, (ti + 2) % 3);
        cp_commit();
    }

    #pragma unroll
    for (int mi = 0; mi < 2; mi++) {
        l0[mi] += __shfl_xor_sync(0xffffffffu, l0[mi], 1);
        l0[mi] += __shfl_xor_sync(0xffffffffu, l0[mi], 2);
        l1[mi] += __shfl_xor_sync(0xffffffffu, l1[mi], 1);
        l1[mi] += __shfl_xor_sync(0xffffffffu, l1[mi], 2);
        const float inv0 = 1.0f / l0[mi];
        const float inv1 = 1.0f / l1[mi];

        const int row0 = qbase + 32 * warp + 16 * mi + lr;
        __half* o0 = attn_out + ((size_t)b * NSEQ + row0) * INNER + h * DHEAD;
        __half* o1 = o0 + (size_t)8 * INNER;
        #pragma unroll
        for (int n = 0; n < 8; n++) {
            const int c = 8 * n + 2 * lc;
            *(uint32_t*)(o0 + c) = pack_h2(oa[mi][n][0] * inv0, oa[mi][n][1] * inv0);
            *(uint32_t*)(o1 + c) = pack_h2(oa[mi][n][2] * inv1, oa[mi][n][3] * inv1);
        }
    }
}

// ---------------------------------------------------------------------------
extern "C" void kernel_launch(void* const* d_in, const int* in_sizes, int n_in,
                              void* d_out, int out_size)
{
    const float* x      = (const float*)d_in[0];
    const float* gamma  = (const float*)d_in[1];
    const float* beta   = (const float*)d_in[2];
    const float* w_qkv  = (const float*)d_in[3];
    const float* w_out  = (const float*)d_in[4];
    float* out = (float*)d_out;

    __half *xn, *qkv, *attn, *wqkvT, *woutT;
    cudaGetSymbolAddress((void**)&xn,    g_xn);
    cudaGetSymbolAddress((void**)&qkv,   g_qkv);
    cudaGetSymbolAddress((void**)&attn,  g_attn);
    cudaGetSymbolAddress((void**)&wqkvT, g_wqkvT);
    cudaGetSymbolAddress((void**)&woutT, g_woutT);

    // 0+1) fused: weight transposes + LayerNorm (one launch)
    prep_kernel<<<NT1 + NT2 + ROWS, 256>>>(x, gamma, beta, w_qkv, w_out,
                                           xn, wqkvT, woutT);

    // 2) QKV projection: [4096,1024] @ [1024,3072], fp16 output (persistent)
    {
        const int tiles = (ROWS / 128) * (QKV_W / 128);   // 768
        const int grid = tiles < 296 ? tiles : 296;
        f16_gemm<<<grid, 256>>>(ROWS, QKV_W, DIM, 1, xn, wqkvT, qkv);
    }

    // 3) attention (128 q-rows per block, 4 warps x m32)
    {
        dim3 grid(NSEQ / 128, BATCH * HEADS);
        attn_mma_kernel<<<grid, 128>>>(qkv, attn);
    }

    // 4) output projection: [4096,1024] @ [1024,1024], fp32 output (persistent)
    {
        const int tiles = (ROWS / 128) * (DIM / 128);     // 256
        const int grid = tiles < 296 ? tiles : 296;
        f16_gemm<<<grid, 256>>>(ROWS, DIM, INNER, 0, attn, woutT, out);
    }
}